// round 17
// baseline (speedup 1.0000x reference)
#include <cuda_runtime.h>
#include <cuda_fp16.h>
#include <math.h>

#define NB 128
#define NT 512
#define Bsz 128
#define Ssz 512
#define Dsz 128
#define Hsz 1024
#define Gsz 4096
#define WSTR 1032          // smem W row stride (halfs); 2064B
#define ASTR 72            // A chunk row stride (halfs); 144B
#define WBYTES (64*WSTR*2)                  // 132096
#define ABUF   (64*ASTR*2)                  // 9216 per buffer
#define AOFF   WBYTES                       // 8 buffers: 73728 (Red overlays: 69632)
#define CSOFF  (AOFF + 8*ABUF)              // 205824: Csm 4KB
#define SMEM_BYTES (CSOFF + 4096)           // 209920 < 232448 cap

#define RECONSZ (Bsz*Ssz*Dsz)      /* 8388608  */
#define ENCSZ   (Bsz*Ssz*Hsz)      /* 67108864 */
#define ENCOFF  RECONSZ
#define TOTSZ   (RECONSZ+ENCSZ+1)  /* 75497473 */

// ---------------- device scratch (static: no allocations) ----------------
__device__ __align__(16) __half  g_Xg[(size_t)Bsz*Ssz*Gsz];     // 512 MB: x@Wih^T + biases
__device__ __align__(16) __half  g_WihH[(size_t)Gsz*Dsz];       // enc Wih fp16
__device__ __align__(16) __half  g_Hbuf[2][(size_t)Bsz*Hsz];    // double-buffered h
__device__ __align__(16) __half  g_Hdec[(size_t)Bsz*Ssz*Hsz];   // 128 MB decoder h's
__device__ __align__(16) __half  g_Wcomb[(size_t)Gsz*Hsz];      // Whh + Wih[:,:128]@out_W
__device__ __align__(16) __half  g_oWh[(size_t)Dsz*Hsz];        // out_W in fp16
__device__ float  g_Bdec0[Gsz];
__device__ float  g_BdecC[Gsz];
__device__ double g_loss;
// init barrier (full grid): monotonic counters
__device__ unsigned g_grpcnt[8];
__device__ unsigned g_rootcnt;
__device__ volatile unsigned g_gen;
// per-row-group barriers (64 CTAs each): 4 subgroups x 16 CTAs
__device__ unsigned g_grpcnt2[2][4];
__device__ unsigned g_rootcnt2[2];
__device__ volatile unsigned g_gen2[2];

// ---------------- full-grid barrier (init only) ----------------
__device__ __forceinline__ void grid_sync_all() {
    __syncthreads();
    if (threadIdx.x == 0) {
        unsigned g = g_gen;
        __threadfence();
        unsigned a = atomicAdd(&g_grpcnt[blockIdx.x >> 4], 1u);
        if ((a & 15u) == 15u) {
            unsigned r = atomicAdd(&g_rootcnt, 1u);
            if ((r & 7u) == 7u) { __threadfence(); g_gen = g + 1u; }
        }
        while (g_gen == g) { __nanosleep(20); }
        __threadfence();
    }
    __syncthreads();
}

// ---------------- per-row-group barrier: 64 CTAs (4 x 16 tree) ----------------
__device__ __forceinline__ void grid_sync_rg(int rg, int cg) {
    __syncthreads();
    if (threadIdx.x == 0) {
        unsigned g = g_gen2[rg];
        __threadfence();
        unsigned a = atomicAdd(&g_grpcnt2[rg][cg >> 4], 1u);
        if ((a & 15u) == 15u) {
            unsigned r = atomicAdd(&g_rootcnt2[rg], 1u);
            if ((r & 3u) == 3u) { __threadfence(); g_gen2[rg] = g + 1u; }
        }
        while (g_gen2[rg] == g) { __nanosleep(20); }
        __threadfence();
    }
    __syncthreads();
}

__device__ __forceinline__ float sigf(float x)  { return 1.f / (1.f + __expf(-x)); }
__device__ __forceinline__ float tanhfast(float x) { return 2.f / (1.f + __expf(-2.f * x)) - 1.f; }

#define NBAR(id) asm volatile("bar.sync %0, 128;" :: "r"(id) : "memory")
#define WAITG0() asm volatile("cp.async.wait_group 0;\n" ::: "memory")
#define WAITG1() asm volatile("cp.async.wait_group 1;\n" ::: "memory")

// ---------------- 64-k chunk loader (by ONE 128-thread k-group) ----------------
__device__ __forceinline__ void loadK(__half* As, int c, int rowbase, int tl,
                                      const __half* __restrict__ hin) {
#pragma unroll
    for (int i = 0; i < 4; i++) {
        int idx = tl + i * 128;          // 512 x 16B segments
        int r   = idx >> 3;
        int kq  = (idx & 7) * 8;
        const __half* gp = hin + (size_t)(rowbase + r) * Hsz + c * 64 + kq;
        unsigned sa = (unsigned)__cvta_generic_to_shared(As + r * ASTR + kq);
        asm volatile("cp.async.cg.shared.global [%0], [%1], 16;\n" :: "r"(sa), "l"(gp));
    }
    asm volatile("cp.async.commit_group;\n" ::: "memory");
}

// ---------------- k-split GEMM: 4 k-groups x (2x2 of 32x32 tiles), K=1024 ----------------
__device__ __forceinline__ void gemm_step(const __half* __restrict__ Ws,
                                          char* smem_raw, int rowbase,
                                          const __half* __restrict__ hin) {
    const int tid  = threadIdx.x;
    const int wid  = tid >> 5, lane = tid & 31;
    const int kg   = wid >> 2, pos = wid & 3;
    const int pr   = pos >> 1, pc = pos & 1;
    const int quad = lane >> 2, tq = lane & 3;
    const int tl   = tid & 127;
    const int barid = kg + 1;

    const int aRow = lane & 15;
    const int aK   = ((lane >> 4) & 1) * 8;
    const int bN   = ((lane >> 4) * 8) + (lane & 7);
    const int bK   = ((lane >> 3) & 1) * 8;

    __half* b0h = (__half*)(smem_raw + AOFF + (2 * kg) * ABUF);
    __half* b1h = (__half*)(smem_raw + AOFF + (2 * kg + 1) * ABUF);

    float acc[2][4][4];
#pragma unroll
    for (int mi = 0; mi < 2; mi++)
#pragma unroll
        for (int ni = 0; ni < 4; ni++)
#pragma unroll
            for (int q = 0; q < 4; q++) acc[mi][ni][q] = 0.f;

    loadK(b0h, kg,     rowbase, tl, hin);
    loadK(b1h, kg + 4, rowbase, tl, hin);
    WAITG1();
    NBAR(barid);

#pragma unroll
    for (int jj = 0; jj < 4; jj++) {
        const int c = kg + 4 * jj;
        const __half* cur = (jj & 1) ? b1h : b0h;
        const __half* bcol = Ws + (size_t)(pc * 32 + bN) * WSTR + c * 64 + bK;
        const __half* arow = cur + (pr * 32 + aRow) * ASTR + aK;
#pragma unroll
        for (int kk = 0; kk < 4; kk++) {
            unsigned bf[2][4];
#pragma unroll
            for (int n2 = 0; n2 < 2; n2++) {
                unsigned ba = (unsigned)__cvta_generic_to_shared(
                                  bcol + n2 * 16 * WSTR + kk * 16);
                asm volatile(
                    "ldmatrix.sync.aligned.m8n8.x4.shared.b16 {%0,%1,%2,%3}, [%4];\n"
                    : "=r"(bf[n2][0]), "=r"(bf[n2][1]), "=r"(bf[n2][2]), "=r"(bf[n2][3])
                    : "r"(ba));
            }
#pragma unroll
            for (int mi = 0; mi < 2; mi++) {
                unsigned a0, a1, a2, a3;
                unsigned aa = (unsigned)__cvta_generic_to_shared(
                                  arow + mi * 16 * ASTR + kk * 16);
                asm volatile(
                    "ldmatrix.sync.aligned.m8n8.x4.shared.b16 {%0,%1,%2,%3}, [%4];\n"
                    : "=r"(a0), "=r"(a1), "=r"(a2), "=r"(a3) : "r"(aa));
#pragma unroll
                for (int n2 = 0; n2 < 2; n2++) {
                    asm volatile(
                        "mma.sync.aligned.m16n8k16.row.col.f32.f16.f16.f32 "
                        "{%0,%1,%2,%3}, {%4,%5,%6,%7}, {%8,%9}, {%0,%1,%2,%3};\n"
                        : "+f"(acc[mi][n2*2][0]), "+f"(acc[mi][n2*2][1]),
                          "+f"(acc[mi][n2*2][2]), "+f"(acc[mi][n2*2][3])
                        : "r"(a0), "r"(a1), "r"(a2), "r"(a3),
                          "r"(bf[n2][0]), "r"(bf[n2][1]));
                    asm volatile(
                        "mma.sync.aligned.m16n8k16.row.col.f32.f16.f16.f32 "
                        "{%0,%1,%2,%3}, {%4,%5,%6,%7}, {%8,%9}, {%0,%1,%2,%3};\n"
                        : "+f"(acc[mi][n2*2+1][0]), "+f"(acc[mi][n2*2+1][1]),
                          "+f"(acc[mi][n2*2+1][2]), "+f"(acc[mi][n2*2+1][3])
                        : "r"(a0), "r"(a1), "r"(a2), "r"(a3),
                          "r"(bf[n2][2]), "r"(bf[n2][3]));
                }
            }
        }
        if (jj < 2) {
            NBAR(barid);
            loadK((jj & 1) ? b1h : b0h, kg + 4 * (jj + 2), rowbase, tl, hin);
            WAITG1();
            NBAR(barid);
        } else if (jj == 2) {
            NBAR(barid);
            WAITG0();
            NBAR(barid);
        }
    }
    __syncthreads();   // all groups done -> A buffers dead, Red overlay safe

    float* red = (float*)(smem_raw + AOFF) + wid * 1088;
#pragma unroll
    for (int mi = 0; mi < 2; mi++)
#pragma unroll
        for (int ni = 0; ni < 4; ni++) {
            int rl = mi * 16 + quad, cl = ni * 8 + tq * 2;
            *(float2*)&red[rl * 34 + cl]       = make_float2(acc[mi][ni][0], acc[mi][ni][1]);
            *(float2*)&red[(rl + 8) * 34 + cl] = make_float2(acc[mi][ni][2], acc[mi][ni][3]);
        }
    __syncthreads();   // partials visible to epilogue
}

// ---------------- merged reduce + LSTM pointwise: 512 threads, 1 half2 each ----------------
__device__ __forceinline__ void epilogue(const float* __restrict__ Red,
                                         float* __restrict__ Csm,
                                         const float2 add[4],
                                         int rg, int cg, int t,
                                         float* __restrict__ out,
                                         __half* __restrict__ hout,
                                         int writeEnc, int writeDec) {
    const int tid = threadIdx.x;
    int row = tid >> 3;            // 0..63
    int jc  = (tid & 7) * 2;       // 0,2..14
    int pr  = row >> 5, r = row & 31;
    int hc  = cg * 16 + jc;
    int bg  = rg * 64 + row;

    float2 gs[4];
#pragma unroll
    for (int gc = 0; gc < 4; gc++) {
        int pc = gc >> 1;
        int c  = (gc & 1) * 16 + jc;
        int off = (pr * 2 + pc) * 1088 + r * 34 + c;
        float2 s = *(const float2*)&Red[off];
#pragma unroll
        for (int kg = 1; kg < 4; kg++) {
            float2 p = *(const float2*)&Red[off + kg * 4 * 1088];
            s.x += p.x; s.y += p.y;
        }
        gs[gc] = s;
    }
    float iv0 = sigf(gs[0].x + add[0].x),     iv1 = sigf(gs[0].y + add[0].y);
    float fv0 = sigf(gs[1].x + add[1].x),     fv1 = sigf(gs[1].y + add[1].y);
    float gv0 = tanhfast(gs[2].x + add[2].x), gv1 = tanhfast(gs[2].y + add[2].y);
    float ov0 = sigf(gs[3].x + add[3].x),     ov1 = sigf(gs[3].y + add[3].y);
    float2 cold = *(const float2*)&Csm[row * 16 + jc];
    float c0 = fv0 * cold.x + iv0 * gv0;
    float c1 = fv1 * cold.y + iv1 * gv1;
    *(float2*)&Csm[row * 16 + jc] = make_float2(c0, c1);
    float h0 = ov0 * tanhfast(c0), h1 = ov1 * tanhfast(c1);
    *(__half2*)&hout[(size_t)bg * Hsz + hc] = __floats2half2_rn(h0, h1);
    if (writeEnc)
        *(float2*)&out[(size_t)ENCOFF + ((size_t)bg * Ssz + t) * Hsz + hc] = make_float2(h0, h1);
    if (writeDec)
        *(__half2*)&g_Hdec[((size_t)bg * Ssz + t) * Hsz + hc] = __floats2half2_rn(h0, h1);
}

// ============================== persistent LSTM kernel ==============================
__global__ void __launch_bounds__(NT, 1)
lstm_ae_kernel(const float* __restrict__ x,
               const float* __restrict__ eWih, const float* __restrict__ eWhh,
               const float* __restrict__ ebih, const float* __restrict__ ebhh,
               const float* __restrict__ dWih, const float* __restrict__ dWhh,
               const float* __restrict__ dbih, const float* __restrict__ dbhh,
               const float* __restrict__ oW,   const float* __restrict__ ob,
               float* __restrict__ out, int out_size) {
    extern __shared__ __align__(16) char smem_raw[];
    __half* Ws  = (__half*)smem_raw;
    float*  Red = (float*)(smem_raw + AOFF);
    float*  Csm = (float*)(smem_raw + CSOFF);

    const int bid = blockIdx.x, tid = threadIdx.x;
    const int rg = bid >> 6;      // batch-row group (0..1)
    const int cg = bid & 63;      // h-col group (0..63)
    const int hasEnc = (out_size >= RECONSZ + ENCSZ) ? 1 : 0;
    const int jc2 = (tid & 7) * 2;
    const int bgE = rg * 64 + (tid >> 3);

    // ================= init =================
    if (bid == 0 && tid == 0) g_loss = 0.0;
    for (int i = bid * NT + tid; i < Bsz * Hsz; i += NB * NT)
        g_Hbuf[0][i] = __float2half(0.f);
    for (int i = bid * NT + tid; i < Dsz * Hsz; i += NB * NT)
        g_oWh[i] = __float2half(oW[i]);
    for (int R = bid * NT + tid; R < Gsz; R += NB * NT) {
        float b0 = dbih[R] + dbhh[R];
        g_Bdec0[R] = b0;
        float s = 0.f;
        const float* wr_ = dWih + (size_t)R * Hsz;
        for (int d = 0; d < 128; d++) s += wr_[d] * ob[d];
        g_BdecC[R] = b0 + s;
    }
    {   // Wcomb = dec_Whh + dec_Wih[:,:128] @ out_W   (rows bid*32..+32)
        int R0 = bid * 32;
        int qr = tid >> 7;
        int k0 = (tid & 127) * 8;
        for (int r = qr * 8; r < qr * 8 + 8; r++) {
            int R = R0 + r;
            const float* wr_ = dWih + (size_t)R * Hsz;
            float a8[8];
#pragma unroll
            for (int q = 0; q < 8; q++) a8[q] = dWhh[(size_t)R * Hsz + k0 + q];
            for (int d = 0; d < 128; d++) {
                float w = wr_[d];
                const float* owp = oW + (size_t)d * Hsz + k0;
#pragma unroll
                for (int q = 0; q < 8; q++) a8[q] += w * owp[q];
            }
#pragma unroll
            for (int q = 0; q < 8; q++)
                g_Wcomb[(size_t)R * Hsz + k0 + q] = __float2half(a8[q]);
        }
    }
    grid_sync_all();

    int par = 0;

    // ================= encoder (K=1024, gates += Xg) =================
    for (int i = tid; i < 1024; i += NT) Csm[i] = 0.f;
    for (int r = 0; r < 64; r++) {
        int R = (r >> 4) * Hsz + cg * 16 + (r & 15);
        for (int k = tid; k < 1024; k += NT)
            Ws[r * WSTR + k] = __float2half(eWhh[(size_t)R * Hsz + k]);
    }
    __syncthreads();
    for (int t = 0; t < Ssz; t++) {
        __half2 xg[4];
        const __half* xgp = g_Xg + (((size_t)bgE * Ssz + t) << 12) + cg * 16 + jc2;
#pragma unroll
        for (int gc = 0; gc < 4; gc++) xg[gc] = *(const __half2*)(xgp + (gc << 10));
        gemm_step(Ws, smem_raw, rg * 64, g_Hbuf[par]);
        float2 add[4];
#pragma unroll
        for (int gc = 0; gc < 4; gc++) add[gc] = __half22float2(xg[gc]);
        epilogue(Red, Csm, add, rg, cg, t, out, g_Hbuf[par ^ 1], hasEnc, 0);
        par ^= 1;
        grid_sync_rg(rg, cg);
    }

    // decoder bias vectors (register-hoisted)
    float2 addC[4];
#pragma unroll
    for (int gc = 0; gc < 4; gc++) {
        int g = (gc << 10) + cg * 16 + jc2;
        addC[gc] = make_float2(g_BdecC[g], g_BdecC[g + 1]);
    }

    // ================= decoder step 0 (input = h_n, weights Wih+Whh) =================
    {
        float2 add0[4];
#pragma unroll
        for (int gc = 0; gc < 4; gc++) {
            int g = (gc << 10) + cg * 16 + jc2;
            add0[gc] = make_float2(g_Bdec0[g], g_Bdec0[g + 1]);
        }
        for (int r = 0; r < 64; r++) {
            int R = (r >> 4) * Hsz + cg * 16 + (r & 15);
            for (int k = tid; k < 1024; k += NT)
                Ws[r * WSTR + k] = __float2half(dWih[(size_t)R * Hsz + k] + dWhh[(size_t)R * Hsz + k]);
        }
        __syncthreads();
        gemm_step(Ws, smem_raw, rg * 64, g_Hbuf[par]);
        epilogue(Red, Csm, add0, rg, cg, 0, out, g_Hbuf[par ^ 1], 0, 1);
        par ^= 1;
        grid_sync_rg(rg, cg);
    }

    // ================= decoder steps 1..511 (folded weights) =================
    for (int s = tid; s < 64 * 128; s += NT) {
        int r  = s >> 7;
        int sg = (s & 127) * 8;
        int R  = (r >> 4) * Hsz + cg * 16 + (r & 15);
        *(uint4*)&Ws[r * WSTR + sg] = *(const uint4*)&g_Wcomb[(size_t)R * Hsz + sg];
    }
    __syncthreads();
    for (int t = 1; t < Ssz; t++) {
        gemm_step(Ws, smem_raw, rg * 64, g_Hbuf[par]);
        epilogue(Red, Csm, addC, rg, cg, t, out, g_Hbuf[par ^ 1], 0, 1);
        par ^= 1;
        grid_sync_rg(rg, cg);
    }
}

// ============== cvt: eWih fp32 -> fp16 ==============
__global__ void cvt_wih_kernel(const float* __restrict__ eWih) {
    for (int i = blockIdx.x * 256 + threadIdx.x; i < Gsz * Dsz; i += gridDim.x * 256)
        g_WihH[i] = __float2half(eWih[i]);
}

// ============== Xg = x @ eWih^T + ebih + ebhh  (parallel pre-pass) ==============
#define XSTR 136           // K=128 rows need stride >= 128; 136 avoids conflicts
__global__ void __launch_bounds__(256)
xg_kernel(const float* __restrict__ x,
          const float* __restrict__ ebih, const float* __restrict__ ebhh) {
    __shared__ __align__(16) __half Asm[64 * XSTR];    // 17408 B
    __shared__ __align__(16) __half Bsm[128 * XSTR];   // 34816 B

    const int tid  = threadIdx.x;
    const int wid  = tid >> 5, lane = tid & 31;
    const int wr   = wid >> 2, wc   = wid & 3;     // 2x4 warps -> 64x128 tile
    const int quad = lane >> 2, tq  = lane & 3;
    const int rb = blockIdx.x, gb = blockIdx.y;
    const int b = rb >> 3, t0 = (rb & 7) << 6, g0 = gb << 7;

    // A: 64 rows (b, t0..t0+63) x 128 d, fp32 -> fp16
#pragma unroll
    for (int j = 0; j < 8; j++) {
        int idx = tid + j * 256;          // 2048 float4s
        int r = idx >> 5, k4 = (idx & 31) * 4;
        float4 v = *(const float4*)(x + ((size_t)b * Ssz + t0 + r) * Dsz + k4);
        *(__half2*)&Asm[r * XSTR + k4]     = __floats2half2_rn(v.x, v.y);
        *(__half2*)&Asm[r * XSTR + k4 + 2] = __floats2half2_rn(v.z, v.w);
    }
    // B: 128 gates x 128 d fp16
#pragma unroll
    for (int j = 0; j < 8; j++) {
        int idx = tid + j * 256;
        int n = idx >> 4, kq = (idx & 15) * 8;
        *(uint4*)&Bsm[n * XSTR + kq] = *(const uint4*)&g_WihH[(size_t)(g0 + n) * Dsz + kq];
    }
    __syncthreads();

    float acc[2][4][4];
#pragma unroll
    for (int mi = 0; mi < 2; mi++)
#pragma unroll
        for (int ni = 0; ni < 4; ni++)
#pragma unroll
            for (int q = 0; q < 4; q++) acc[mi][ni][q] = 0.f;

#pragma unroll
    for (int kk = 0; kk < 8; kk++) {
        unsigned bfr[4][2];
#pragma unroll
        for (int ni = 0; ni < 4; ni++) {
            const __half* bp = Bsm + (wc * 32 + ni * 8 + quad) * XSTR + kk * 16 + tq * 2;
            bfr[ni][0] = *(const unsigned*)bp;
            bfr[ni][1] = *(const unsigned*)(bp + 8);
        }
#pragma unroll
        for (int mi = 0; mi < 2; mi++) {
            const __half* ap = Asm + (wr * 32 + mi * 16 + quad) * XSTR + kk * 16 + tq * 2;
            unsigned a0 = *(const unsigned*)ap;
            unsigned a1 = *(const unsigned*)(ap + 8 * XSTR);
            unsigned a2 = *(const unsigned*)(ap + 8);
            unsigned a3 = *(const unsigned*)(ap + 8 * XSTR + 8);
#pragma unroll
            for (int ni = 0; ni < 4; ni++)
                asm volatile(
                    "mma.sync.aligned.m16n8k16.row.col.f32.f16.f16.f32 "
                    "{%0,%1,%2,%3}, {%4,%5,%6,%7}, {%8,%9}, {%0,%1,%2,%3};\n"
                    : "+f"(acc[mi][ni][0]), "+f"(acc[mi][ni][1]),
                      "+f"(acc[mi][ni][2]), "+f"(acc[mi][ni][3])
                    : "r"(a0), "r"(a1), "r"(a2), "r"(a3),
                      "r"(bfr[ni][0]), "r"(bfr[ni][1]));
        }
    }

#pragma unroll
    for (int mi = 0; mi < 2; mi++)
#pragma unroll
        for (int ni = 0; ni < 4; ni++) {
            int rowl = wr * 32 + mi * 16 + quad;
            int col  = wc * 32 + ni * 8 + tq * 2;
            int g = g0 + col;
            float b0 = ebih[g] + ebhh[g], b1 = ebih[g + 1] + ebhh[g + 1];
#pragma unroll
            for (int h = 0; h < 2; h++) {
                int rr = rowl + h * 8;
                *(__half2*)&g_Xg[((size_t)b * Ssz + t0 + rr) * (size_t)Gsz + g] =
                    __floats2half2_rn(acc[mi][ni][h * 2] + b0, acc[mi][ni][h * 2 + 1] + b1);
            }
        }
}

// ============== recon = Hdec @ out_W^T + out_b  (+ fused loss) ==============
#define RASTR 72
__global__ void __launch_bounds__(256)
recon_kernel(const float* __restrict__ x, const float* __restrict__ ob,
             float* __restrict__ out, int out_size) {
    __shared__ __align__(16) __half Asm[64 * RASTR];
    __shared__ __align__(16) __half Wsm[128 * RASTR];

    const int tid  = threadIdx.x;
    const int wid  = tid >> 5, lane = tid & 31;
    const int wr   = wid >> 2, wc   = wid & 3;
    const int quad = lane >> 2, tq  = lane & 3;
    const int rowbase = blockIdx.x * 64;
    const int doRecon = (out_size >= RECONSZ) ? 1 : 0;

    float acc[2][4][4];
#pragma unroll
    for (int mi = 0; mi < 2; mi++)
#pragma unroll
        for (int ni = 0; ni < 4; ni++)
#pragma unroll
            for (int q = 0; q < 4; q++) acc[mi][ni][q] = 0.f;

    for (int c = 0; c < 16; c++) {
        const int kabs = c * 64;
#pragma unroll
        for (int j = 0; j < 2; j++) {
            int idx = tid + j * 256;
            int r = idx >> 3, kq = (idx & 7) * 8;
            *(uint4*)&Asm[r * RASTR + kq] =
                *(const uint4*)(g_Hdec + (size_t)(rowbase + r) * Hsz + kabs + kq);
        }
#pragma unroll
        for (int j = 0; j < 4; j++) {
            int idx = tid + j * 256;
            int n = idx >> 3, kq = (idx & 7) * 8;
            *(uint4*)&Wsm[n * RASTR + kq] =
                *(const uint4*)(g_oWh + (size_t)n * Hsz + kabs + kq);
        }
        __syncthreads();
#pragma unroll
        for (int kk = 0; kk < 4; kk++) {
            unsigned bfr[4][2];
#pragma unroll
            for (int ni = 0; ni < 4; ni++) {
                const __half* bp = Wsm + (wc * 32 + ni * 8 + quad) * RASTR + kk * 16 + tq * 2;
                bfr[ni][0] = *(const unsigned*)bp;
                bfr[ni][1] = *(const unsigned*)(bp + 8);
            }
#pragma unroll
            for (int mi = 0; mi < 2; mi++) {
                const __half* ap = Asm + (wr * 32 + mi * 16 + quad) * RASTR + kk * 16 + tq * 2;
                unsigned a0 = *(const unsigned*)ap;
                unsigned a1 = *(const unsigned*)(ap + 8 * RASTR);
                unsigned a2 = *(const unsigned*)(ap + 8);
                unsigned a3 = *(const unsigned*)(ap + 8 * RASTR + 8);
#pragma unroll
                for (int ni = 0; ni < 4; ni++)
                    asm volatile(
                        "mma.sync.aligned.m16n8k16.row.col.f32.f16.f16.f32 "
                        "{%0,%1,%2,%3}, {%4,%5,%6,%7}, {%8,%9}, {%0,%1,%2,%3};\n"
                        : "+f"(acc[mi][ni][0]), "+f"(acc[mi][ni][1]),
                          "+f"(acc[mi][ni][2]), "+f"(acc[mi][ni][3])
                        : "r"(a0), "r"(a1), "r"(a2), "r"(a3),
                          "r"(bfr[ni][0]), "r"(bfr[ni][1]));
            }
        }
        __syncthreads();
    }

    float lsum = 0.f;
#pragma unroll
    for (int mi = 0; mi < 2; mi++)
#pragma unroll
        for (int ni = 0; ni < 4; ni++) {
            int row = rowbase + wr * 32 + mi * 16 + quad;
            int col = wc * 32 + ni * 8 + tq * 2;
            float b0 = ob[col], b1 = ob[col + 1];
#pragma unroll
            for (int half_ = 0; half_ < 2; half_++) {
                int rr = row + half_ * 8;
                float v0 = acc[mi][ni][half_ * 2]     + b0;
                float v1 = acc[mi][ni][half_ * 2 + 1] + b1;
                size_t o = (size_t)rr * Dsz + col;
                float d0 = v0 - x[o], d1 = v1 - x[o + 1];
                lsum += d0 * d0 + d1 * d1;
                if (doRecon) { out[o] = v0; out[o + 1] = v1; }
            }
        }
#pragma unroll
    for (int off = 16; off > 0; off >>= 1)
        lsum += __shfl_xor_sync(0xffffffffu, lsum, off);
    if (lane == 0) atomicAdd(&g_loss, (double)lsum);
}

__global__ void loss_finish(float* __restrict__ out, int out_size) {
    if (out_size >= TOTSZ) out[RECONSZ + ENCSZ] = (float)(g_loss * (1.0 / 128.0));
}

// ============================== launch ==============================
extern "C" void kernel_launch(void* const* d_in, const int* in_sizes, int n_in,
                              void* d_out, int out_size) {
    const float* x     = (const float*)d_in[0];
    const float* eWih  = (const float*)d_in[1];
    const float* eWhh  = (const float*)d_in[2];
    const float* ebih  = (const float*)d_in[3];
    const float* ebhh  = (const float*)d_in[4];
    const float* dWih  = (const float*)d_in[5];
    const float* dWhh  = (const float*)d_in[6];
    const float* dbih  = (const float*)d_in[7];
    const float* dbhh  = (const float*)d_in[8];
    const float* oW    = (const float*)d_in[9];
    const float* ob    = (const float*)d_in[10];
    float* out = (float*)d_out;

    cudaFuncSetAttribute(lstm_ae_kernel,
                         cudaFuncAttributeMaxDynamicSharedMemorySize, SMEM_BYTES);

    cvt_wih_kernel<<<256, 256>>>(eWih);
    xg_kernel<<<dim3(1024, 32), 256>>>(x, ebih, ebhh);
    lstm_ae_kernel<<<NB, NT, SMEM_BYTES>>>(x, eWih, eWhh, ebih, ebhh,
                                           dWih, dWhh, dbih, dbhh, oW, ob,
                                           out, out_size);
    recon_kernel<<<(Bsz * Ssz) / 64, 256>>>(x, ob, out, out_size);
    loss_finish<<<1, 1>>>(out, out_size);
}